// round 1
// baseline (speedup 1.0000x reference)
#include <cuda_runtime.h>
#include <cstddef>

#define BB     32768
#define T_IN   1024
#define STEPS  512
#define NBLK   128
#define NTHR   256

// Deterministic loss reduction scratch: one partial per block.
__device__ float g_partial[NBLK];

struct W {
    float wi0, wi1, wi2, wi3;
    float wh0, wh1, wh2, wh3;
    float b0,  b1,  b2,  b3;
};

__device__ __forceinline__ float fast_sig(float x) {
    // 1 / (1 + e^-x): FMUL + MUFU.EX2 + FADD + MUFU.RCP
    return __fdividef(1.0f, 1.0f + __expf(-x));
}
__device__ __forceinline__ float fast_tanh(float x) {
    // tanh(x) = 2*sigmoid(2x) - 1
    return fmaf(2.0f, fast_sig(x + x), -1.0f);
}

__device__ __forceinline__ void lstm_step(float xv, float& h, float& c, const W& w) {
    float ig = fmaf(xv, w.wi0, fmaf(h, w.wh0, w.b0));
    float fg = fmaf(xv, w.wi1, fmaf(h, w.wh1, w.b1));
    float gg = fmaf(xv, w.wi2, fmaf(h, w.wh2, w.b2));
    float og = fmaf(xv, w.wi3, fmaf(h, w.wh3, w.b3));
    float i = fast_sig(ig);
    float f = fast_sig(fg);
    float o = fast_sig(og);
    float g = fast_tanh(gg);
    c = fmaf(f, c, i * g);
    h = o * fast_tanh(c);
}

__global__ __launch_bounds__(NTHR, 1) void lstm_kernel(
    const float* __restrict__ x,   const float* __restrict__ tt,
    const float* __restrict__ h0,  const float* __restrict__ c0,
    const float* __restrict__ w_ih, const float* __restrict__ w_hh,
    const float* __restrict__ b_ih, const float* __restrict__ b_hh,
    float* __restrict__ pred)
{
    const int b = blockIdx.x * NTHR + threadIdx.x;

    W w;
    w.wi0 = w_ih[0]; w.wi1 = w_ih[1]; w.wi2 = w_ih[2]; w.wi3 = w_ih[3];
    w.wh0 = w_hh[0]; w.wh1 = w_hh[1]; w.wh2 = w_hh[2]; w.wh3 = w_hh[3];
    w.b0 = b_ih[0] + b_hh[0];
    w.b1 = b_ih[1] + b_hh[1];
    w.b2 = b_ih[2] + b_hh[2];
    w.b3 = b_ih[3] + b_hh[3];

    float h = h0[b];
    float c = c0[b];

    // ---------------- open loop: 1024 steps, float4 loads, 16-step prefetch ----
    const float4* xv = reinterpret_cast<const float4*>(x + (size_t)b * T_IN);
    float4 v0 = xv[0], v1 = xv[1], v2 = xv[2], v3 = xv[3];

    #pragma unroll 1
    for (int it = 0; it < T_IN / 16; it++) {
        float4 n0, n1, n2, n3;
        const bool more = (it < T_IN / 16 - 1);
        if (more) {
            const float4* p = xv + 4 * it + 4;
            n0 = p[0]; n1 = p[1]; n2 = p[2]; n3 = p[3];
        }
        lstm_step(v0.x, h, c, w); lstm_step(v0.y, h, c, w);
        lstm_step(v0.z, h, c, w); lstm_step(v0.w, h, c, w);
        lstm_step(v1.x, h, c, w); lstm_step(v1.y, h, c, w);
        lstm_step(v1.z, h, c, w); lstm_step(v1.w, h, c, w);
        lstm_step(v2.x, h, c, w); lstm_step(v2.y, h, c, w);
        lstm_step(v2.z, h, c, w); lstm_step(v2.w, h, c, w);
        lstm_step(v3.x, h, c, w); lstm_step(v3.y, h, c, w);
        lstm_step(v3.z, h, c, w); lstm_step(v3.w, h, c, w);
        if (more) { v0 = n0; v1 = n1; v2 = n2; v3 = n3; }
    }
    float xin = v3.w;  // x[b, T_IN-1] feeds the first closed-loop step

    // ---------------- closed loop: 512 autoregressive steps --------------------
    const float4* tv = reinterpret_cast<const float4*>(tt + (size_t)b * STEPS);
    float* po = pred ? (pred + (size_t)b * STEPS) : nullptr;
    float lacc = 0.0f;

    float4 u0 = tv[0], u1 = tv[1], u2 = tv[2], u3 = tv[3];
    int s = 0;

    #pragma unroll 1
    for (int it = 0; it < STEPS / 16; it++) {
        float4 m0, m1, m2, m3;
        const bool more = (it < STEPS / 16 - 1);
        if (more) {
            const float4* p = tv + 4 * it + 4;
            m0 = p[0]; m1 = p[1]; m2 = p[2]; m3 = p[3];
        }
        #define CSTEP(TVAL)                                    \
        {                                                      \
            lstm_step(xin, h, c, w);                           \
            float d = h - (TVAL);                              \
            lacc = fmaf(d, d, lacc);                           \
            if (po) po[s] = h;                                 \
            s++;                                               \
            xin = h;                                           \
        }
        CSTEP(u0.x) CSTEP(u0.y) CSTEP(u0.z) CSTEP(u0.w)
        CSTEP(u1.x) CSTEP(u1.y) CSTEP(u1.z) CSTEP(u1.w)
        CSTEP(u2.x) CSTEP(u2.y) CSTEP(u2.z) CSTEP(u2.w)
        CSTEP(u3.x) CSTEP(u3.y) CSTEP(u3.z) CSTEP(u3.w)
        #undef CSTEP
        if (more) { u0 = m0; u1 = m1; u2 = m2; u3 = m3; }
    }

    // ---------------- deterministic loss reduction -----------------------------
    #pragma unroll
    for (int off = 16; off; off >>= 1)
        lacc += __shfl_xor_sync(0xffffffffu, lacc, off);

    __shared__ float ss[NTHR / 32];
    if ((threadIdx.x & 31) == 0) ss[threadIdx.x >> 5] = lacc;
    __syncthreads();
    if (threadIdx.x == 0) {
        float s2 = 0.0f;
        #pragma unroll
        for (int i = 0; i < NTHR / 32; i++) s2 += ss[i];
        g_partial[blockIdx.x] = s2;
    }
}

__global__ void finalize_kernel(float* loss_out) {
    // Single thread, fixed order -> bitwise deterministic.
    double s = 0.0;
    for (int i = 0; i < NBLK; i++) s += (double)g_partial[i];
    *loss_out = (float)(s / (double)BB);
}

extern "C" void kernel_launch(void* const* d_in, const int* in_sizes, int n_in,
                              void* d_out, int out_size) {
    const float* x    = (const float*)d_in[0];
    const float* t    = (const float*)d_in[1];
    const float* h0   = (const float*)d_in[2];
    const float* c0   = (const float*)d_in[3];
    const float* w_ih = (const float*)d_in[4];
    const float* w_hh = (const float*)d_in[5];
    const float* b_ih = (const float*)d_in[6];
    const float* b_hh = (const float*)d_in[7];

    float* out = (float*)d_out;
    const long long total = (long long)BB * STEPS;

    float* loss_out = nullptr;
    float* pred_out = nullptr;
    if ((long long)out_size == total + 1) {        // (loss, pred_seq) flattened
        loss_out = out;
        pred_out = out + 1;
    } else if ((long long)out_size == total) {     // pred only
        pred_out = out;
    } else if (out_size == 1) {                    // loss only
        loss_out = out;
    } else {                                       // fallback: loss first
        loss_out = out;
        if (out_size > 1) pred_out = out + 1;
    }

    lstm_kernel<<<NBLK, NTHR>>>(x, t, h0, c0, w_ih, w_hh, b_ih, b_hh, pred_out);
    if (loss_out) finalize_kernel<<<1, 1>>>(loss_out);
}

// round 2
// speedup vs baseline: 1.4174x; 1.4174x over previous
#include <cuda_runtime.h>
#include <cstddef>

#define BB     32768
#define T_IN   1024
#define STEPS  512
#define NBLK   256
#define NTHR   128

__device__ float g_partial[NBLK];
__device__ unsigned int g_count = 0;

struct W {
    // half-scaled combined (wi+wh) weights for sigmoid gates (closed loop),
    // plus separates for the open loop.
    float wii_h, wif_h, wio_h, wig;      // w_ih rows (i,f,o half-scaled; g full)
    float whi_h, whf_h, who_h, whg;      // w_hh rows
    float wci_h, wcf_h, wco_h, wcg;      // combined wi+wh (closed loop)
    float bi_h, bf_h, bo_h, bg;          // biases (i,f,o half-scaled; g full)
};

__device__ __forceinline__ float htanh(float x) {
    float y;
    asm("tanh.approx.f32 %0, %1;" : "=f"(y) : "f"(x));
    return y;
}

// sigmoid(2*a) where a is the pre-halved gate value: 0.5 + 0.5*tanh(a)
__device__ __forceinline__ float sig_from_half(float a) {
    return fmaf(0.5f, htanh(a), 0.5f);
}

// Open-loop step: x term computed off the h-critical-path.
__device__ __forceinline__ void step_open(float xv, float& h, float& c, const W& w) {
    float pi = fmaf(xv, w.wii_h, w.bi_h);
    float pf = fmaf(xv, w.wif_h, w.bf_h);
    float po = fmaf(xv, w.wio_h, w.bo_h);
    float pg = fmaf(xv, w.wig,   w.bg);
    float i = sig_from_half(fmaf(h, w.whi_h, pi));
    float f = sig_from_half(fmaf(h, w.whf_h, pf));
    float o = sig_from_half(fmaf(h, w.who_h, po));
    float g = htanh(fmaf(h, w.whg, pg));
    c = fmaf(f, c, i * g);
    h = o * htanh(c);
}

// Closed-loop step: x_in == h, so one FFMA per gate from h.
__device__ __forceinline__ void step_closed(float& h, float& c, const W& w) {
    float i = sig_from_half(fmaf(h, w.wci_h, w.bi_h));
    float f = sig_from_half(fmaf(h, w.wcf_h, w.bf_h));
    float o = sig_from_half(fmaf(h, w.wco_h, w.bo_h));
    float g = htanh(fmaf(h, w.wcg, w.bg));
    c = fmaf(f, c, i * g);
    h = o * htanh(c);
}

__global__ __launch_bounds__(NTHR, 2) void lstm_kernel(
    const float* __restrict__ x,   const float* __restrict__ tt,
    const float* __restrict__ h0,  const float* __restrict__ c0,
    const float* __restrict__ w_ih, const float* __restrict__ w_hh,
    const float* __restrict__ b_ih, const float* __restrict__ b_hh,
    float* __restrict__ pred, float* __restrict__ loss_out)
{
    const int b = blockIdx.x * NTHR + threadIdx.x;

    W w;
    {
        float wi0 = w_ih[0], wi1 = w_ih[1], wi2 = w_ih[2], wi3 = w_ih[3];
        float wh0 = w_hh[0], wh1 = w_hh[1], wh2 = w_hh[2], wh3 = w_hh[3];
        float b0 = b_ih[0] + b_hh[0];
        float b1 = b_ih[1] + b_hh[1];
        float b2 = b_ih[2] + b_hh[2];
        float b3 = b_ih[3] + b_hh[3];
        // PyTorch gate order: i, f, g, o = rows 0,1,2,3
        w.wii_h = 0.5f * wi0; w.whi_h = 0.5f * wh0; w.bi_h = 0.5f * b0;
        w.wif_h = 0.5f * wi1; w.whf_h = 0.5f * wh1; w.bf_h = 0.5f * b1;
        w.wig   = wi2;        w.whg   = wh2;        w.bg   = b2;
        w.wio_h = 0.5f * wi3; w.who_h = 0.5f * wh3; w.bo_h = 0.5f * b3;
        w.wci_h = w.wii_h + w.whi_h;
        w.wcf_h = w.wif_h + w.whf_h;
        w.wcg   = w.wig   + w.whg;
        w.wco_h = w.wio_h + w.who_h;
    }

    float h = h0[b];
    float c = c0[b];

    // ---------------- open loop: 1024 steps, streaming float4 + prefetch ------
    const float4* xv = reinterpret_cast<const float4*>(x + (size_t)b * T_IN);
    float4 v0 = __ldcs(xv + 0), v1 = __ldcs(xv + 1),
           v2 = __ldcs(xv + 2), v3 = __ldcs(xv + 3);

    #pragma unroll 1
    for (int it = 0; it < T_IN / 16; it++) {
        float4 n0, n1, n2, n3;
        const bool more = (it < T_IN / 16 - 1);
        if (more) {
            const float4* p = xv + 4 * it + 4;
            n0 = __ldcs(p + 0); n1 = __ldcs(p + 1);
            n2 = __ldcs(p + 2); n3 = __ldcs(p + 3);
        }
        step_open(v0.x, h, c, w); step_open(v0.y, h, c, w);
        step_open(v0.z, h, c, w); step_open(v0.w, h, c, w);
        step_open(v1.x, h, c, w); step_open(v1.y, h, c, w);
        step_open(v1.z, h, c, w); step_open(v1.w, h, c, w);
        step_open(v2.x, h, c, w); step_open(v2.y, h, c, w);
        step_open(v2.z, h, c, w); step_open(v2.w, h, c, w);
        step_open(v3.x, h, c, w); step_open(v3.y, h, c, w);
        step_open(v3.z, h, c, w); step_open(v3.w, h, c, w);
        if (more) { v0 = n0; v1 = n1; v2 = n2; v3 = n3; }
    }

    // first closed-loop input is x[b, T_IN-1]
    step_open(v3.w, h, c, w);   // step 0 of closed loop uses x_in = last x

    // ---------------- closed loop: remaining 511 autoregressive steps ---------
    const float4* tv = reinterpret_cast<const float4*>(tt + (size_t)b * STEPS);
    float* po = pred ? (pred + (size_t)b * STEPS) : nullptr;
    float lacc = 0.0f;

    // handle step 0's loss/store (pred[0] = h after the step above)
    float4 u0 = __ldcs(tv + 0), u1 = __ldcs(tv + 1),
           u2 = __ldcs(tv + 2), u3 = __ldcs(tv + 3);
    {
        float d = h - u0.x;
        lacc = fmaf(d, d, lacc);
        if (po) __stcs(po + 0, h);
    }

    int s = 1;
    #pragma unroll 1
    for (int it = 0; it < STEPS / 16; it++) {
        float4 m0, m1, m2, m3;
        const bool more = (it < STEPS / 16 - 1);
        if (more) {
            const float4* p = tv + 4 * it + 4;
            m0 = __ldcs(p + 0); m1 = __ldcs(p + 1);
            m2 = __ldcs(p + 2); m3 = __ldcs(p + 3);
        }
        // this iteration consumes targets u0..u3 shifted by one (s = 16*it+1 .. +16)
        #define CSTEP(TVAL)                                     \
        {                                                       \
            if (s < STEPS) {                                    \
                step_closed(h, c, w);                           \
                float d = h - (TVAL);                           \
                lacc = fmaf(d, d, lacc);                        \
                if (po) __stcs(po + s, h);                      \
                s++;                                            \
            }                                                   \
        }
        CSTEP(u0.y) CSTEP(u0.z) CSTEP(u0.w)
        CSTEP(u1.x) CSTEP(u1.y) CSTEP(u1.z) CSTEP(u1.w)
        CSTEP(u2.x) CSTEP(u2.y) CSTEP(u2.z) CSTEP(u2.w)
        CSTEP(u3.x) CSTEP(u3.y) CSTEP(u3.z) CSTEP(u3.w)
        // cross into the next prefetched group for the 16th target of this round
        if (more) { CSTEP(m0.x) u0 = m0; u1 = m1; u2 = m2; u3 = m3; }
        #undef CSTEP
    }

    // ---------------- deterministic in-kernel loss reduction -------------------
    #pragma unroll
    for (int off = 16; off; off >>= 1)
        lacc += __shfl_xor_sync(0xffffffffu, lacc, off);

    __shared__ float ss[NTHR / 32];
    if ((threadIdx.x & 31) == 0) ss[threadIdx.x >> 5] = lacc;
    __syncthreads();

    __shared__ bool is_last;
    if (threadIdx.x == 0) {
        float s2 = 0.0f;
        #pragma unroll
        for (int i = 0; i < NTHR / 32; i++) s2 += ss[i];
        g_partial[blockIdx.x] = s2;
        __threadfence();
        unsigned int ticket = atomicAdd(&g_count, 1u);
        is_last = (ticket == NBLK - 1);
    }
    __syncthreads();

    if (is_last && loss_out) {
        // fixed-order tree reduction over NBLK partials -> deterministic
        __shared__ float red[NTHR];
        float v = g_partial[threadIdx.x] + g_partial[threadIdx.x + NTHR];
        red[threadIdx.x] = v;
        __syncthreads();
        #pragma unroll
        for (int stride = NTHR / 2; stride > 0; stride >>= 1) {
            if (threadIdx.x < stride) red[threadIdx.x] += red[threadIdx.x + stride];
            __syncthreads();
        }
        if (threadIdx.x == 0) {
            *loss_out = red[0] / (float)BB;
            g_count = 0;            // reset for next graph replay
        }
    } else if (is_last) {
        if (threadIdx.x == 0) g_count = 0;
    }
}

extern "C" void kernel_launch(void* const* d_in, const int* in_sizes, int n_in,
                              void* d_out, int out_size) {
    const float* x    = (const float*)d_in[0];
    const float* t    = (const float*)d_in[1];
    const float* h0   = (const float*)d_in[2];
    const float* c0   = (const float*)d_in[3];
    const float* w_ih = (const float*)d_in[4];
    const float* w_hh = (const float*)d_in[5];
    const float* b_ih = (const float*)d_in[6];
    const float* b_hh = (const float*)d_in[7];

    float* out = (float*)d_out;
    const long long total = (long long)BB * STEPS;

    float* loss_out = nullptr;
    float* pred_out = nullptr;
    if ((long long)out_size == total + 1) {        // (loss, pred_seq) flattened
        loss_out = out;
        pred_out = out + 1;
    } else if ((long long)out_size == total) {     // pred only
        pred_out = out;
    } else if (out_size == 1) {                    // loss only
        loss_out = out;
    } else {
        loss_out = out;
        if (out_size > 1) pred_out = out + 1;
    }

    lstm_kernel<<<NBLK, NTHR>>>(x, t, h0, c0, w_ih, w_hh, b_ih, b_hh,
                                pred_out, loss_out);
}

// round 3
// speedup vs baseline: 2.9955x; 2.1134x over previous
#include <cuda_runtime.h>
#include <cstddef>

#define BB     32768
#define T_IN   1024
#define STEPS  512
#define NBLK   256
#define NTHR   128
#define NWARP  (NTHR / 32)

__device__ float g_partial[NBLK];
__device__ unsigned int g_count = 0;

struct W {
    float wii_h, wif_h, wio_h, wig;      // w_ih (i,f,o half-scaled; g full)
    float whi_h, whf_h, who_h, whg;      // w_hh
    float wci_h, wcf_h, wco_h, wcg;      // combined wi+wh (closed loop)
    float bi_h, bf_h, bo_h, bg;          // biases
};

__device__ __forceinline__ float htanh(float x) {
    float y;
    asm("tanh.approx.f32 %0, %1;" : "=f"(y) : "f"(x));
    return y;
}
__device__ __forceinline__ float sig_from_half(float a) {
    // sigmoid(2a) = 0.5 + 0.5*tanh(a)
    return fmaf(0.5f, htanh(a), 0.5f);
}

__device__ __forceinline__ void step_open(float xv, float& h, float& c, const W& w) {
    float pi = fmaf(xv, w.wii_h, w.bi_h);
    float pf = fmaf(xv, w.wif_h, w.bf_h);
    float po = fmaf(xv, w.wio_h, w.bo_h);
    float pg = fmaf(xv, w.wig,   w.bg);
    float i = sig_from_half(fmaf(h, w.whi_h, pi));
    float f = sig_from_half(fmaf(h, w.whf_h, pf));
    float o = sig_from_half(fmaf(h, w.who_h, po));
    float g = htanh(fmaf(h, w.whg, pg));
    c = fmaf(f, c, i * g);
    h = o * htanh(c);
}

__device__ __forceinline__ void step_closed(float& h, float& c, const W& w) {
    float i = sig_from_half(fmaf(h, w.wci_h, w.bi_h));
    float f = sig_from_half(fmaf(h, w.wcf_h, w.bf_h));
    float o = sig_from_half(fmaf(h, w.wco_h, w.bo_h));
    float g = htanh(fmaf(h, w.wcg, w.bg));
    c = fmaf(f, c, i * g);
    h = o * htanh(c);
}

__global__ __launch_bounds__(NTHR, 2) void lstm_kernel(
    const float* __restrict__ x,   const float* __restrict__ tt,
    const float* __restrict__ h0,  const float* __restrict__ c0,
    const float* __restrict__ w_ih, const float* __restrict__ w_hh,
    const float* __restrict__ b_ih, const float* __restrict__ b_hh,
    float* __restrict__ pred, float* __restrict__ loss_out)
{
    const int tid  = threadIdx.x;
    const int lane = tid & 31;
    const int wid  = tid >> 5;
    const int b    = blockIdx.x * NTHR + tid;
    const int wb   = blockIdx.x * NTHR + (wid << 5);   // warp's base batch row

    // per-warp transpose tile: [row=batch-lane][col=step], +1 pad -> conflict-free
    __shared__ float tile[NWARP][32][33];
    float (*T)[33] = tile[wid];

    W w;
    {
        float wi0 = w_ih[0], wi1 = w_ih[1], wi2 = w_ih[2], wi3 = w_ih[3];
        float wh0 = w_hh[0], wh1 = w_hh[1], wh2 = w_hh[2], wh3 = w_hh[3];
        float b0 = b_ih[0] + b_hh[0];
        float b1 = b_ih[1] + b_hh[1];
        float b2 = b_ih[2] + b_hh[2];
        float b3 = b_ih[3] + b_hh[3];
        // gate order: i, f, g, o
        w.wii_h = 0.5f * wi0; w.whi_h = 0.5f * wh0; w.bi_h = 0.5f * b0;
        w.wif_h = 0.5f * wi1; w.whf_h = 0.5f * wh1; w.bf_h = 0.5f * b1;
        w.wig   = wi2;        w.whg   = wh2;        w.bg   = b2;
        w.wio_h = 0.5f * wi3; w.who_h = 0.5f * wh3; w.bo_h = 0.5f * b3;
        w.wci_h = w.wii_h + w.whi_h;
        w.wcf_h = w.wif_h + w.whf_h;
        w.wcg   = w.wig   + w.whg;
        w.wco_h = w.wio_h + w.who_h;
    }

    float h = h0[b];
    float c = c0[b];

    // ---------------- open loop: 1024 steps in 32-step coalesced chunks -------
    const float* xw = x + (size_t)wb * T_IN;
    #pragma unroll 1
    for (int ch = 0; ch < T_IN / 32; ch++) {
        const int s0 = ch * 32;
        __syncwarp();
        #pragma unroll
        for (int r = 0; r < 32; r++)                 // coalesced row loads
            T[r][lane] = __ldcs(xw + (size_t)r * T_IN + s0 + lane);
        __syncwarp();
        #pragma unroll
        for (int k = 0; k < 32; k++)
            step_open(T[lane][k], h, c, w);
    }
    const float xlast = T[lane][31];                 // x[b, T_IN-1]

    // ---------------- closed loop: 512 steps in 32-step chunks ----------------
    const float* tw = tt + (size_t)wb * STEPS;
    float* pw = pred ? (pred + (size_t)wb * STEPS) : nullptr;
    float lacc = 0.0f;

    #pragma unroll 1
    for (int ch = 0; ch < STEPS / 32; ch++) {
        const int s0 = ch * 32;
        __syncwarp();
        #pragma unroll
        for (int r = 0; r < 32; r++)                 // coalesced target loads
            T[r][lane] = __ldcs(tw + (size_t)r * STEPS + s0 + lane);
        __syncwarp();

        if (ch == 0) {
            // step 0 uses x_in = x[:, -1]
            step_open(xlast, h, c, w);
            { float tv = T[lane][0]; float d = h - tv; lacc = fmaf(d, d, lacc); T[lane][0] = h; }
            #pragma unroll
            for (int k = 1; k < 32; k++) {
                step_closed(h, c, w);
                float tv = T[lane][k]; float d = h - tv; lacc = fmaf(d, d, lacc); T[lane][k] = h;
            }
        } else {
            #pragma unroll
            for (int k = 0; k < 32; k++) {
                step_closed(h, c, w);
                float tv = T[lane][k]; float d = h - tv; lacc = fmaf(d, d, lacc); T[lane][k] = h;
            }
        }
        __syncwarp();
        if (pw) {
            #pragma unroll
            for (int r = 0; r < 32; r++)             // coalesced pred stores
                __stcs(pw + (size_t)r * STEPS + s0 + lane, T[r][lane]);
        }
    }

    // ---------------- deterministic in-kernel loss reduction ------------------
    #pragma unroll
    for (int off = 16; off; off >>= 1)
        lacc += __shfl_xor_sync(0xffffffffu, lacc, off);

    __shared__ float ss[NWARP];
    if (lane == 0) ss[wid] = lacc;
    __syncthreads();

    __shared__ bool is_last;
    if (tid == 0) {
        float s2 = 0.0f;
        #pragma unroll
        for (int i = 0; i < NWARP; i++) s2 += ss[i];
        g_partial[blockIdx.x] = s2;
        __threadfence();
        unsigned int ticket = atomicAdd(&g_count, 1u);
        is_last = (ticket == NBLK - 1);
    }
    __syncthreads();

    if (is_last) {
        if (loss_out) {
            __shared__ float red[NTHR];
            float v = g_partial[tid] + g_partial[tid + NTHR];
            red[tid] = v;
            __syncthreads();
            #pragma unroll
            for (int stride = NTHR / 2; stride > 0; stride >>= 1) {
                if (tid < stride) red[tid] += red[tid + stride];
                __syncthreads();
            }
            if (tid == 0) {
                *loss_out = red[0] / (float)BB;
                g_count = 0;
            }
        } else if (tid == 0) {
            g_count = 0;
        }
    }
}

extern "C" void kernel_launch(void* const* d_in, const int* in_sizes, int n_in,
                              void* d_out, int out_size) {
    const float* x    = (const float*)d_in[0];
    const float* t    = (const float*)d_in[1];
    const float* h0   = (const float*)d_in[2];
    const float* c0   = (const float*)d_in[3];
    const float* w_ih = (const float*)d_in[4];
    const float* w_hh = (const float*)d_in[5];
    const float* b_ih = (const float*)d_in[6];
    const float* b_hh = (const float*)d_in[7];

    float* out = (float*)d_out;
    const long long total = (long long)BB * STEPS;

    float* loss_out = nullptr;
    float* pred_out = nullptr;
    if ((long long)out_size == total + 1) {
        loss_out = out;
        pred_out = out + 1;
    } else if ((long long)out_size == total) {
        pred_out = out;
    } else if (out_size == 1) {
        loss_out = out;
    } else {
        loss_out = out;
        if (out_size > 1) pred_out = out + 1;
    }

    lstm_kernel<<<NBLK, NTHR>>>(x, t, h0, c0, w_ih, w_hh, b_ih, b_hh,
                                pred_out, loss_out);
}

// round 4
// speedup vs baseline: 3.7137x; 1.2398x over previous
#include <cuda_runtime.h>
#include <cstddef>

#define BB     32768
#define T_IN   1024
#define STEPS  512
#define NTHR   256
#define NBLK   (BB / NTHR)          // 128 blocks -> exactly 1 block / SM, 8 warps uniform
#define NWARP  (NTHR / 32)

__device__ float g_partial[NBLK];
__device__ unsigned int g_count = 0;

struct W {
    float wii_h, wif_h, wio_h, wig;      // w_ih (i,f,o half-scaled; g full)
    float whi_h, whf_h, who_h, whg;      // w_hh
    float wci_h, wcf_h, wco_h, wcg;      // combined wi+wh (closed loop)
    float bi_h, bf_h, bo_h, bg;          // biases
};

__device__ __forceinline__ float htanh(float x) {
    float y;
    asm("tanh.approx.f32 %0, %1;" : "=f"(y) : "f"(x));
    return y;
}
__device__ __forceinline__ float sig_from_half(float a) {
    // sigmoid(2a) = 0.5 + 0.5*tanh(a)
    return fmaf(0.5f, htanh(a), 0.5f);
}

__device__ __forceinline__ void step_open(float xv, float& h, float& c, const W& w) {
    float pi = fmaf(xv, w.wii_h, w.bi_h);
    float pf = fmaf(xv, w.wif_h, w.bf_h);
    float po = fmaf(xv, w.wio_h, w.bo_h);
    float pg = fmaf(xv, w.wig,   w.bg);
    float i = sig_from_half(fmaf(h, w.whi_h, pi));
    float f = sig_from_half(fmaf(h, w.whf_h, pf));
    float o = sig_from_half(fmaf(h, w.who_h, po));
    float g = htanh(fmaf(h, w.whg, pg));
    c = fmaf(f, c, i * g);
    h = o * htanh(c);
}

__device__ __forceinline__ void step_closed(float& h, float& c, const W& w) {
    float i = sig_from_half(fmaf(h, w.wci_h, w.bi_h));
    float f = sig_from_half(fmaf(h, w.wcf_h, w.bf_h));
    float o = sig_from_half(fmaf(h, w.wco_h, w.bo_h));
    float g = htanh(fmaf(h, w.wcg, w.bg));
    c = fmaf(f, c, i * g);
    h = o * htanh(c);
}

__global__ __launch_bounds__(NTHR, 1) void lstm_kernel(
    const float* __restrict__ x,   const float* __restrict__ tt,
    const float* __restrict__ h0,  const float* __restrict__ c0,
    const float* __restrict__ w_ih, const float* __restrict__ w_hh,
    const float* __restrict__ b_ih, const float* __restrict__ b_hh,
    float* __restrict__ pred, float* __restrict__ loss_out)
{
    const int tid  = threadIdx.x;
    const int lane = tid & 31;
    const int wid  = tid >> 5;
    const int b    = blockIdx.x * NTHR + tid;
    const int wb   = blockIdx.x * NTHR + (wid << 5);   // warp's base batch row

    // per-warp transpose tile: [row=batch-lane][col=step], +1 pad -> conflict-free
    __shared__ float tile[NWARP][32][33];
    float (*T)[33] = tile[wid];

    W w;
    {
        float wi0 = w_ih[0], wi1 = w_ih[1], wi2 = w_ih[2], wi3 = w_ih[3];
        float wh0 = w_hh[0], wh1 = w_hh[1], wh2 = w_hh[2], wh3 = w_hh[3];
        float b0 = b_ih[0] + b_hh[0];
        float b1 = b_ih[1] + b_hh[1];
        float b2 = b_ih[2] + b_hh[2];
        float b3 = b_ih[3] + b_hh[3];
        // gate order: i, f, g, o
        w.wii_h = 0.5f * wi0; w.whi_h = 0.5f * wh0; w.bi_h = 0.5f * b0;
        w.wif_h = 0.5f * wi1; w.whf_h = 0.5f * wh1; w.bf_h = 0.5f * b1;
        w.wig   = wi2;        w.whg   = wh2;        w.bg   = b2;
        w.wio_h = 0.5f * wi3; w.who_h = 0.5f * wh3; w.bo_h = 0.5f * b3;
        w.wci_h = w.wii_h + w.whi_h;
        w.wcf_h = w.wif_h + w.whf_h;
        w.wcg   = w.wig   + w.whg;
        w.wco_h = w.wio_h + w.who_h;
    }

    float h = h0[b];
    float c = c0[b];

    const float* xw = x + (size_t)wb * T_IN;
    const float* tw = tt + (size_t)wb * STEPS;
    float* pw = pred ? (pred + (size_t)wb * STEPS) : nullptr;

    // prefetch registers: p[r] = element (row wb+r, col chunk*32+lane)
    float p[32];

    // ---------------- open loop: 1024 steps, register-prefetched chunks -------
    #pragma unroll
    for (int r = 0; r < 32; r++)
        p[r] = __ldcs(xw + (size_t)r * T_IN + lane);

    #pragma unroll 1
    for (int ch = 0; ch < T_IN / 32; ch++) {
        __syncwarp();
        #pragma unroll
        for (int r = 0; r < 32; r++)
            T[r][lane] = p[r];
        __syncwarp();

        if (ch < T_IN / 32 - 1) {
            const float* src = xw + (size_t)(ch + 1) * 32;
            #pragma unroll
            for (int r = 0; r < 32; r++)
                p[r] = __ldcs(src + (size_t)r * T_IN + lane);
        } else {
            // last open chunk: prefetch first closed-loop target chunk
            #pragma unroll
            for (int r = 0; r < 32; r++)
                p[r] = __ldcs(tw + (size_t)r * STEPS + lane);
        }

        #pragma unroll
        for (int k = 0; k < 32; k++)
            step_open(T[lane][k], h, c, w);
    }
    const float xlast = T[lane][31];                 // x[b, T_IN-1]

    // ---------------- closed loop: 512 steps, prefetch + coalesced pred -------
    float lacc = 0.0f;

    #pragma unroll 1
    for (int ch = 0; ch < STEPS / 32; ch++) {
        const int s0 = ch * 32;
        __syncwarp();
        #pragma unroll
        for (int r = 0; r < 32; r++)
            T[r][lane] = p[r];
        __syncwarp();

        if (ch < STEPS / 32 - 1) {
            const float* src = tw + (size_t)(ch + 1) * 32;
            #pragma unroll
            for (int r = 0; r < 32; r++)
                p[r] = __ldcs(src + (size_t)r * STEPS + lane);
        }

        if (ch == 0) {
            step_open(xlast, h, c, w);               // step 0 uses x[:, -1]
            { float tv = T[lane][0]; float d = h - tv; lacc = fmaf(d, d, lacc); T[lane][0] = h; }
            #pragma unroll
            for (int k = 1; k < 32; k++) {
                step_closed(h, c, w);
                float tv = T[lane][k]; float d = h - tv; lacc = fmaf(d, d, lacc); T[lane][k] = h;
            }
        } else {
            #pragma unroll
            for (int k = 0; k < 32; k++) {
                step_closed(h, c, w);
                float tv = T[lane][k]; float d = h - tv; lacc = fmaf(d, d, lacc); T[lane][k] = h;
            }
        }
        __syncwarp();
        if (pw) {
            #pragma unroll
            for (int r = 0; r < 32; r++)             // coalesced pred stores
                __stcs(pw + (size_t)r * STEPS + s0 + lane, T[r][lane]);
        }
    }

    // ---------------- deterministic in-kernel loss reduction ------------------
    #pragma unroll
    for (int off = 16; off; off >>= 1)
        lacc += __shfl_xor_sync(0xffffffffu, lacc, off);

    __shared__ float ss[NWARP];
    if (lane == 0) ss[wid] = lacc;
    __syncthreads();

    __shared__ bool is_last;
    if (tid == 0) {
        float s2 = 0.0f;
        #pragma unroll
        for (int i = 0; i < NWARP; i++) s2 += ss[i];
        g_partial[blockIdx.x] = s2;
        __threadfence();
        unsigned int ticket = atomicAdd(&g_count, 1u);
        is_last = (ticket == NBLK - 1);
    }
    __syncthreads();

    if (is_last) {
        if (loss_out) {
            __shared__ float red[NBLK];
            if (tid < NBLK) red[tid] = g_partial[tid];
            __syncthreads();
            #pragma unroll
            for (int stride = NBLK / 2; stride > 0; stride >>= 1) {
                if (tid < stride) red[tid] += red[tid + stride];
                __syncthreads();
            }
            if (tid == 0) {
                *loss_out = red[0] / (float)BB;
                g_count = 0;
            }
        } else if (tid == 0) {
            g_count = 0;
        }
    }
}

extern "C" void kernel_launch(void* const* d_in, const int* in_sizes, int n_in,
                              void* d_out, int out_size) {
    const float* x    = (const float*)d_in[0];
    const float* t    = (const float*)d_in[1];
    const float* h0   = (const float*)d_in[2];
    const float* c0   = (const float*)d_in[3];
    const float* w_ih = (const float*)d_in[4];
    const float* w_hh = (const float*)d_in[5];
    const float* b_ih = (const float*)d_in[6];
    const float* b_hh = (const float*)d_in[7];

    float* out = (float*)d_out;
    const long long total = (long long)BB * STEPS;

    float* loss_out = nullptr;
    float* pred_out = nullptr;
    if ((long long)out_size == total + 1) {
        loss_out = out;
        pred_out = out + 1;
    } else if ((long long)out_size == total) {
        pred_out = out;
    } else if (out_size == 1) {
        loss_out = out;
    } else {
        loss_out = out;
        if (out_size > 1) pred_out = out + 1;
    }

    lstm_kernel<<<NBLK, NTHR>>>(x, t, h0, c0, w_ih, w_hh, b_ih, b_hh,
                                pred_out, loss_out);
}